// round 12
// baseline (speedup 1.0000x reference)
#include <cuda_runtime.h>
#include <cuda_bf16.h>
#include <cuda_fp16.h>
#include <mma.h>
#include <cstdint>

using namespace nvcuda;

// Problem constants (fixed-shape problem, from reference_code)
#define N_NODES 100000
#define D_FEAT  256
#define H1      128
#define H2      64
#define N_EDGES 1600000

#define SCAN_BLK 1024
#define N_SCAN_BLOCKS ((N_NODES + SCAN_BLK - 1) / SCAN_BLK)   // 98

// Scratch buffers (device globals: allocation-free scratch).
__device__ __half g_xw0h[(size_t)N_NODES * H1];  // X @ W0, fp16 (gather operand)
__device__ float  g_h1 [(size_t)N_NODES * H1];   // spmm1 result fp32 (pre-relu)
__device__ __half g_hw1h[(size_t)N_NODES * H2];  // relu(h1) @ W1, fp16 (gather operand)
__device__ int    g_is64;                        // edge index dtype flag

// CSR (by dst) built fresh each launch; col+weight packed in one int2
__device__ int   g_cnt [N_NODES];                // histogram, then cursor
__device__ int   g_ptr [N_NODES + 1];            // row pointers
__device__ int   g_bsum[N_SCAN_BLOCKS];
__device__ int   g_flag[N_SCAN_BLOCKS];          // lookback ready flags
__device__ int2  g_edge[N_EDGES];                // {col, __float_as_int(w)}

// ---------------------------------------------------------------------------
// f32x2 packed math (sm_103a; PTX-only — ptxas never auto-fuses)
// ---------------------------------------------------------------------------
__device__ __forceinline__ unsigned long long pack2(float x, float y) {
    unsigned long long r;
    asm("mov.b64 %0, {%1, %2};" : "=l"(r) : "f"(x), "f"(y));
    return r;
}
__device__ __forceinline__ void unpack2(unsigned long long v, float& x, float& y) {
    asm("mov.b64 {%0, %1}, %2;" : "=f"(x), "=f"(y) : "l"(v));
}
__device__ __forceinline__ void fma2(unsigned long long& d,
                                     unsigned long long a,
                                     unsigned long long b) {
    asm("fma.rn.f32x2 %0, %1, %2, %0;" : "+l"(d) : "l"(a), "l"(b));
}

// ---------------------------------------------------------------------------
// dtype probe (thread 0) + zero histogram + zero scan flags
// ---------------------------------------------------------------------------
__global__ void detect_zero_kernel(const void* __restrict__ src) {
    int i = blockIdx.x * blockDim.x + threadIdx.x;
    if (i < N_NODES) g_cnt[i] = 0;
    if (i < N_SCAN_BLOCKS) g_flag[i] = 0;
    if (i == 0) {
        const long long* p = (const long long*)src;
        int ok = 1;
        for (int k = 0; k < 64; k++) {
            long long v = p[k];
            if (v < 0 || v >= N_NODES) { ok = 0; break; }
        }
        g_is64 = ok;
    }
}

__device__ __forceinline__ int load_idx(const void* p, int e, int is64) {
    return is64 ? (int)((const long long*)p)[e] : ((const int*)p)[e];
}

// ---------------------------------------------------------------------------
// CSR build: histogram -> single-pass scan (parallel lookback) -> scatter
// ---------------------------------------------------------------------------
__global__ void hist_kernel(const void* __restrict__ dst, int E) {
    int e = blockIdx.x * blockDim.x + threadIdx.x;
    if (e >= E) return;
    int d = load_idx(dst, e, g_is64);
    if ((unsigned)d < N_NODES) atomicAdd(&g_cnt[d], 1);
}

// One kernel: per-block inclusive scan + publish + parallel lookback.
// 98 blocks of 1024 threads — all resident in wave 1 (<=148 SMs),
// so spinning on predecessor flags cannot deadlock.
__global__ void scan_fused_kernel(int E) {
    __shared__ int s[SCAN_BLK];
    __shared__ int pre[128];
    const int b   = blockIdx.x;
    const int tid = threadIdx.x;
    const int i   = b * SCAN_BLK + tid;

    int v = (i < N_NODES) ? g_cnt[i] : 0;
    s[tid] = v;
    __syncthreads();
#pragma unroll
    for (int o = 1; o < SCAN_BLK; o <<= 1) {
        int t = (tid >= o) ? s[tid - o] : 0;
        __syncthreads();
        s[tid] += t;
        __syncthreads();
    }
    int inc = s[tid];

    if (tid == SCAN_BLK - 1) {
        g_bsum[b] = inc;
        __threadfence();
        atomicExch(&g_flag[b], 1);
    }

    // parallel lookback: thread t polls predecessor t's total
    if (tid < 128) {
        int sum = 0;
        if (tid < b) {
            while (atomicAdd(&g_flag[tid], 0) == 0) {}
            sum = g_bsum[tid];
        }
        pre[tid] = sum;
    }
    __syncthreads();
#pragma unroll
    for (int o = 64; o >= 1; o >>= 1) {
        if (tid < o) pre[tid] += pre[tid + o];
        __syncthreads();
    }
    int prefix = pre[0];

    if (i < N_NODES) {
        int p = prefix + inc - v;   // exclusive global prefix
        g_ptr[i] = p;
        g_cnt[i] = p;               // cursor for scatter
    }
    if (i == 0) g_ptr[N_NODES] = E;
}

__global__ void scatter_kernel(const void* __restrict__ src,
                               const void* __restrict__ dst,
                               const float* __restrict__ w, int E) {
    int e = blockIdx.x * blockDim.x + threadIdx.x;
    if (e >= E) return;
    int is64 = g_is64;
    int s = load_idx(src, e, is64);
    int d = load_idx(dst, e, is64);
    if ((unsigned)s >= N_NODES || (unsigned)d >= N_NODES) return;
    int pos = atomicAdd(&g_cnt[d], 1);
    g_edge[pos] = make_int2(s, __float_as_int(w[e]));
}

// ---------------------------------------------------------------------------
// GEMM1: tensor-core (wmma fp16 in / fp32 accum), output fp16.
// xw0h[M,128] = fp16( X[M,256] @ W0[256,128] )
// ---------------------------------------------------------------------------
#define G1_LDA 40    // 32 + 8 halves
#define G1_LDB 136   // 128 + 8 halves
#define G1_LDC 72    // 64 + 8 floats (epilogue staging, per column-half)
#define G1_C_BYTES  (128 * G1_LDC * 4)                     // 36864

__global__ void gemm1_wmma_kernel(const float* __restrict__ X,
                                  const float* __restrict__ W0) {
    __shared__ __align__(16) char smem[G1_C_BYTES];        // 36 KB (union)
    half*  As = (half*)smem;                               // [128][40]
    half*  Bs = (half*)(smem + 128 * G1_LDA * 2);          // [32][136]
    float* Cs = (float*)smem;                              // [128][72]

    const int tid   = threadIdx.x;
    const int warp  = tid >> 5;
    const int warpM = warp >> 1;        // 0..3
    const int warpN = warp & 1;         // 0..1
    const int bm    = blockIdx.x * 128;

    wmma::fragment<wmma::accumulator, 16, 16, 16, float> c[2][4];
#pragma unroll
    for (int i = 0; i < 2; i++)
#pragma unroll
        for (int j = 0; j < 4; j++) wmma::fill_fragment(c[i][j], 0.f);

    for (int k0 = 0; k0 < D_FEAT; k0 += 32) {
        // As: 128x32 fp32 -> fp16
#pragma unroll
        for (int t = 0; t < 4; t++) {
            int chunk = tid + t * 256;
            int row = chunk >> 3;
            int c4  = chunk & 7;
            int grow = bm + row;
            float4 v = make_float4(0.f, 0.f, 0.f, 0.f);
            if (grow < N_NODES)
                v = *(const float4*)(X + (size_t)grow * D_FEAT + k0 + c4 * 4);
            __half2 h0 = __floats2half2_rn(v.x, v.y);
            __half2 h1 = __floats2half2_rn(v.z, v.w);
            uint2 pk;
            pk.x = *(unsigned*)&h0;
            pk.y = *(unsigned*)&h1;
            *(uint2*)(As + (size_t)row * G1_LDA + c4 * 4) = pk;
        }
        // Bs: 32x128 fp32 -> fp16
#pragma unroll
        for (int t = 0; t < 4; t++) {
            int chunk = tid + t * 256;
            int row = chunk >> 5;
            int c4  = chunk & 31;
            float4 v = *(const float4*)(W0 + (size_t)(k0 + row) * H1 + c4 * 4);
            __half2 h0 = __floats2half2_rn(v.x, v.y);
            __half2 h1 = __floats2half2_rn(v.z, v.w);
            uint2 pk;
            pk.x = *(unsigned*)&h0;
            pk.y = *(unsigned*)&h1;
            *(uint2*)(Bs + (size_t)row * G1_LDB + c4 * 4) = pk;
        }
        __syncthreads();

#pragma unroll
        for (int kk = 0; kk < 32; kk += 16) {
            wmma::fragment<wmma::matrix_a, 16, 16, 16, half, wmma::row_major> a[2];
            wmma::fragment<wmma::matrix_b, 16, 16, 16, half, wmma::row_major> b[4];
#pragma unroll
            for (int i = 0; i < 2; i++)
                wmma::load_matrix_sync(a[i],
                    As + (size_t)(warpM * 32 + i * 16) * G1_LDA + kk, G1_LDA);
#pragma unroll
            for (int j = 0; j < 4; j++)
                wmma::load_matrix_sync(b[j],
                    Bs + (size_t)kk * G1_LDB + warpN * 64 + j * 16, G1_LDB);
#pragma unroll
            for (int i = 0; i < 2; i++)
#pragma unroll
                for (int j = 0; j < 4; j++)
                    wmma::mma_sync(c[i][j], a[i], b[j], c[i][j]);
        }
        __syncthreads();
    }

    // Epilogue in two column-halves through smem staging
#pragma unroll
    for (int p = 0; p < 2; p++) {
        if (warpN == p) {
#pragma unroll
            for (int i = 0; i < 2; i++)
#pragma unroll
                for (int j = 0; j < 4; j++)
                    wmma::store_matrix_sync(
                        Cs + (size_t)(warpM * 32 + i * 16) * G1_LDC + j * 16,
                        c[i][j], G1_LDC, wmma::mem_row_major);
        }
        __syncthreads();
#pragma unroll
        for (int t = 0; t < 8; t++) {
            int chunk = tid + t * 256;
            int row = chunk >> 4;
            int c4  = chunk & 15;
            int grow = bm + row;
            if (grow < N_NODES) {
                const float* s = Cs + (size_t)row * G1_LDC + c4 * 4;
                __half2 h0 = __floats2half2_rn(s[0], s[1]);
                __half2 h1 = __floats2half2_rn(s[2], s[3]);
                uint2 pk;
                pk.x = *(unsigned*)&h0;
                pk.y = *(unsigned*)&h1;
                *(uint2*)(g_xw0h + (size_t)grow * H1 + p * 64 + c4 * 4) = pk;
            }
        }
        __syncthreads();
    }
}

// ---------------------------------------------------------------------------
// GEMM2 (f32x2, register-blocked, fp32 A-path — precision-critical):
// hw1h[M,64] = fp16( relu(h1) @ W1 )
// ---------------------------------------------------------------------------
template<int BM, int BN, int BK, int TM, int TN, bool RELU_A>
__device__ __forceinline__ void gemm_body_h(const float* __restrict__ A,
                                            const float* __restrict__ B,
                                            __half* __restrict__ C,
                                            int M, int K, int N)
{
    __shared__ float As[BK][BM];   // transposed A tile
    __shared__ float Bs[BK][BN];

    constexpr int THREADS = (BM / TM) * (BN / TN);   // 256
    const int tid = threadIdx.x;
    const int bm  = blockIdx.x * BM;
    const int tx  = tid % (BN / TN);
    const int ty  = tid / (BN / TN);

    unsigned long long acc2[TM][TN / 2];
#pragma unroll
    for (int i = 0; i < TM; i++)
#pragma unroll
        for (int j = 0; j < TN / 2; j++) acc2[i][j] = 0ull;

    for (int k0 = 0; k0 < K; k0 += BK) {
        constexpr int A_ELEMS = BM * BK;
#pragma unroll
        for (int off = 0; off < A_ELEMS; off += THREADS * 4) {
            int idx = off + tid * 4;
            if (idx < A_ELEMS) {
                int ar  = idx / BK;
                int ac  = idx % BK;
                int grow = bm + ar;
                float4 v = make_float4(0.f, 0.f, 0.f, 0.f);
                if (grow < M)
                    v = *(const float4*)(A + (size_t)grow * K + k0 + ac);
                if (RELU_A) {
                    v.x = fmaxf(v.x, 0.f); v.y = fmaxf(v.y, 0.f);
                    v.z = fmaxf(v.z, 0.f); v.w = fmaxf(v.w, 0.f);
                }
                As[ac + 0][ar] = v.x;
                As[ac + 1][ar] = v.y;
                As[ac + 2][ar] = v.z;
                As[ac + 3][ar] = v.w;
            }
        }
        constexpr int B_ELEMS = BK * BN;
#pragma unroll
        for (int off = 0; off < B_ELEMS; off += THREADS * 4) {
            int idx = off + tid * 4;
            if (idx < B_ELEMS) {
                int br = idx / BN;
                int bc = idx % BN;
                *(float4*)&Bs[br][bc] =
                    *(const float4*)(B + (size_t)(k0 + br) * N + bc);
            }
        }
        __syncthreads();

#pragma unroll
        for (int kk = 0; kk < BK; kk++) {
            unsigned long long b2[TN / 2];
#pragma unroll
            for (int j = 0; j < TN / 2; j++)
                b2[j] = *(const unsigned long long*)&Bs[kk][tx * TN + 2 * j];
#pragma unroll
            for (int i = 0; i < TM; i++) {
                float a = As[kk][ty * TM + i];
                unsigned long long a2 = pack2(a, a);
#pragma unroll
                for (int j = 0; j < TN / 2; j++)
                    fma2(acc2[i][j], a2, b2[j]);
            }
        }
        __syncthreads();
    }

#pragma unroll
    for (int i = 0; i < TM; i++) {
        int row = bm + ty * TM + i;
        if (row < M) {
            __half2 h[TN / 2];
#pragma unroll
            for (int j = 0; j < TN / 2; j++) {
                float lo, hi;
                unpack2(acc2[i][j], lo, hi);
                h[j] = __floats2half2_rn(lo, hi);
            }
#pragma unroll
            for (int j = 0; j < TN / 2; j += 2)
                *(uint2*)(C + (size_t)row * N + tx * TN + 2 * j) =
                    *(uint2*)&h[j];
        }
    }
}

__global__ void gemm2_kernel(const float* __restrict__ W1) {
    gemm_body_h<128, 64, 32, 8, 4, true>(g_h1, W1, g_hw1h, N_NODES, H1, H2);
}

// ---------------------------------------------------------------------------
// CSR SPMM layer 1: h1[r] = sum_e w_e * xw0[col_e], F=128 halves.
// One warp per row; 8-edge batches for deep MLP.
// ---------------------------------------------------------------------------
__global__ void spmm1_csr_kernel()
{
    int warp = (int)(((long long)blockIdx.x * blockDim.x + threadIdx.x) >> 5);
    int lane = threadIdx.x & 31;
    if (warp >= N_NODES) return;
    int p  = g_ptr[warp];
    int pe = g_ptr[warp + 1];
    const uint2* __restrict__ h4 = (const uint2*)g_xw0h;   // 4 halves / elem
    float4 acc = make_float4(0.f, 0.f, 0.f, 0.f);

    for (; p + 8 <= pe; p += 8) {
        int2  e[8];
        uint2 r[8];
#pragma unroll
        for (int j = 0; j < 8; j++) e[j] = g_edge[p + j];
#pragma unroll
        for (int j = 0; j < 8; j++) r[j] = h4[(size_t)e[j].x * 32 + lane];
#pragma unroll
        for (int j = 0; j < 8; j++) {
            float w = __int_as_float(e[j].y);
            float2 a = __half22float2(*(__half2*)&r[j].x);
            float2 b = __half22float2(*(__half2*)&r[j].y);
            acc.x += w * a.x; acc.y += w * a.y;
            acc.z += w * b.x; acc.w += w * b.y;
        }
    }
    if (p + 4 <= pe) {
        int2  e[4];
        uint2 r[4];
#pragma unroll
        for (int j = 0; j < 4; j++) e[j] = g_edge[p + j];
#pragma unroll
        for (int j = 0; j < 4; j++) r[j] = h4[(size_t)e[j].x * 32 + lane];
#pragma unroll
        for (int j = 0; j < 4; j++) {
            float w = __int_as_float(e[j].y);
            float2 a = __half22float2(*(__half2*)&r[j].x);
            float2 b = __half22float2(*(__half2*)&r[j].y);
            acc.x += w * a.x; acc.y += w * a.y;
            acc.z += w * b.x; acc.w += w * b.y;
        }
        p += 4;
    }
    for (; p < pe; p++) {
        int2 e = g_edge[p];
        float w = __int_as_float(e.y);
        uint2 r = h4[(size_t)e.x * 32 + lane];
        float2 a = __half22float2(*(__half2*)&r.x);
        float2 b = __half22float2(*(__half2*)&r.y);
        acc.x += w * a.x; acc.y += w * a.y;
        acc.z += w * b.x; acc.w += w * b.y;
    }
    ((float4*)g_h1)[(size_t)warp * 32 + lane] = acc;
}

// ---------------------------------------------------------------------------
// CSR SPMM layer 2 fused with relu + softmax, F=64 halves; 8-edge batches.
// ---------------------------------------------------------------------------
__global__ void spmm2_softmax_kernel(float* __restrict__ out)
{
    int warp = (int)(((long long)blockIdx.x * blockDim.x + threadIdx.x) >> 5);
    int lane = threadIdx.x & 31;
    if (warp >= N_NODES) return;
    int p  = g_ptr[warp];
    int pe = g_ptr[warp + 1];
    const unsigned* __restrict__ h2p = (const unsigned*)g_hw1h;  // 2 halves
    float2 acc = make_float2(0.f, 0.f);

    for (; p + 8 <= pe; p += 8) {
        int2     e[8];
        unsigned r[8];
#pragma unroll
        for (int j = 0; j < 8; j++) e[j] = g_edge[p + j];
#pragma unroll
        for (int j = 0; j < 8; j++) r[j] = h2p[(size_t)e[j].x * 32 + lane];
#pragma unroll
        for (int j = 0; j < 8; j++) {
            float w = __int_as_float(e[j].y);
            float2 v = __half22float2(*(__half2*)&r[j]);
            acc.x += w * v.x; acc.y += w * v.y;
        }
    }
    if (p + 4 <= pe) {
        int2     e[4];
        unsigned r[4];
#pragma unroll
        for (int j = 0; j < 4; j++) e[j] = g_edge[p + j];
#pragma unroll
        for (int j = 0; j < 4; j++) r[j] = h2p[(size_t)e[j].x * 32 + lane];
#pragma unroll
        for (int j = 0; j < 4; j++) {
            float w = __int_as_float(e[j].y);
            float2 v = __half22float2(*(__half2*)&r[j]);
            acc.x += w * v.x; acc.y += w * v.y;
        }
        p += 4;
    }
    for (; p < pe; p++) {
        int2 e = g_edge[p];
        float w = __int_as_float(e.y);
        unsigned r = h2p[(size_t)e.x * 32 + lane];
        float2 v = __half22float2(*(__half2*)&r);
        acc.x += w * v.x; acc.y += w * v.y;
    }

    // relu + softmax over the 64 values held by the warp
    float v0 = fmaxf(acc.x, 0.f);
    float v1 = fmaxf(acc.y, 0.f);
    float m = fmaxf(v0, v1);
#pragma unroll
    for (int o = 16; o; o >>= 1) m = fmaxf(m, __shfl_xor_sync(~0u, m, o));
    float e0 = __expf(v0 - m);
    float e1 = __expf(v1 - m);
    float s = e0 + e1;
#pragma unroll
    for (int o = 16; o; o >>= 1) s += __shfl_xor_sync(~0u, s, o);
    float inv = 1.f / s;
    ((float2*)out)[(size_t)warp * 32 + lane] = make_float2(e0 * inv, e1 * inv);
}

// ---------------------------------------------------------------------------
// Launch: fork-join streams — gemm1 (tensor) overlaps CSR build (memory)
// ---------------------------------------------------------------------------
extern "C" void kernel_launch(void* const* d_in, const int* in_sizes, int n_in,
                              void* d_out, int out_size)
{
    // Identify inputs by element count (same logic that passed R3-R9).
    const float* x  = nullptr;
    const float* W0 = nullptr;
    const float* W1 = nullptr;
    const void*  edge_buf[3] = {nullptr, nullptr, nullptr};
    int          edge_sz [3] = {0, 0, 0};
    int n_edge_bufs = 0;

    for (int i = 0; i < n_in; i++) {
        int sz = in_sizes[i];
        if (sz == N_NODES * D_FEAT)       x  = (const float*)d_in[i];
        else if (sz == D_FEAT * H1)       W0 = (const float*)d_in[i];
        else if (sz == H1 * H2)           W1 = (const float*)d_in[i];
        else if (n_edge_bufs < 3) {
            edge_buf[n_edge_bufs] = d_in[i];
            edge_sz [n_edge_bufs] = sz;
            n_edge_bufs++;
        }
    }
    const void*  esrc = edge_buf[0];
    const void*  edst = edge_buf[1];
    const float* ew   = (const float*)edge_buf[2];
    if (edge_sz[0] != edge_sz[1] || edge_sz[1] != edge_sz[2]) {
        int wi = 0;
        if (edge_sz[1] < edge_sz[wi]) wi = 1;
        if (edge_sz[2] < edge_sz[wi]) wi = 2;
        const void* rest[2]; int r = 0;
        for (int i = 0; i < 3; i++) if (i != wi) rest[r++] = edge_buf[i];
        esrc = rest[0]; edst = rest[1];
        ew   = (const float*)edge_buf[wi];
    }
    float* out = (float*)d_out;
    const int E = N_EDGES;

    const int EBLK = (E + 255) / 256;
    const int NBLK = (N_NODES + 255) / 256;
    const int WBLK = (int)(((long long)N_NODES * 32 + 255) / 256);

    // Fork-join side stream for gemm1 (created/destroyed per call; no caching)
    cudaStream_t s2 = nullptr;
    cudaEvent_t  evFork = nullptr, evJoin = nullptr;
    bool overlap = (cudaStreamCreateWithFlags(&s2, cudaStreamNonBlocking)
                        == cudaSuccess);
    if (overlap) {
        overlap = (cudaEventCreateWithFlags(&evFork, cudaEventDisableTiming)
                       == cudaSuccess) &&
                  (cudaEventCreateWithFlags(&evJoin, cudaEventDisableTiming)
                       == cudaSuccess);
    }

    if (overlap) {
        cudaEventRecord(evFork, 0);            // fork from capture stream
        cudaStreamWaitEvent(s2, evFork, 0);
        gemm1_wmma_kernel<<<(N_NODES + 127) / 128, 256, 0, s2>>>(x, W0);
        cudaEventRecord(evJoin, s2);
    } else {
        gemm1_wmma_kernel<<<(N_NODES + 127) / 128, 256>>>(x, W0);
    }

    // CSR build on the main (capture) stream
    detect_zero_kernel<<<NBLK, 256>>>(esrc);
    hist_kernel<<<EBLK, 256>>>(edst, E);
    scan_fused_kernel<<<N_SCAN_BLOCKS, SCAN_BLK>>>(E);
    scatter_kernel<<<EBLK, 256>>>(esrc, edst, ew, E);

    if (overlap)
        cudaStreamWaitEvent(0, evJoin, 0);     // join before spmm1

    // layer 1 aggregate: h1 = A @ xw0 (CSR gather, fp32 acc)
    spmm1_csr_kernel<<<WBLK, 256>>>();

    // layer 2: hw1h = fp16(relu(h1) @ W1), f32x2 path (precision-critical)
    gemm2_kernel<<<(N_NODES + 127) / 128, 256>>>(W1);

    // layer 2 aggregate + softmax: out = softmax(relu(A @ hw1))
    spmm2_softmax_kernel<<<WBLK, 256>>>(out);

    if (evFork) cudaEventDestroy(evFork);
    if (evJoin) cudaEventDestroy(evJoin);
    if (s2)     cudaStreamDestroy(s2);
}

// round 15
// speedup vs baseline: 1.0732x; 1.0732x over previous
#include <cuda_runtime.h>
#include <cuda_bf16.h>
#include <cuda_fp16.h>
#include <mma.h>
#include <cstdint>

using namespace nvcuda;

// Problem constants (fixed-shape problem, from reference_code)
#define N_NODES 100000
#define D_FEAT  256
#define H1      128
#define H2      64
#define N_EDGES 1600000

#define SCAN_BLK 1024
#define N_SCAN_BLOCKS ((N_NODES + SCAN_BLK - 1) / SCAN_BLK)   // 98

// Scratch buffers (device globals: allocation-free scratch).
__device__ __half g_xw0h[(size_t)N_NODES * H1];  // X @ W0, fp16 (gather operand)
__device__ float  g_h1 [(size_t)N_NODES * H1];   // spmm1 result fp32 (pre-relu)
__device__ __half g_hw1h[(size_t)N_NODES * H2];  // relu(h1) @ W1, fp16 (gather operand)
__device__ int    g_is64;                        // edge index dtype flag

// CSR (by dst) built fresh each launch; col+weight packed in one int2
__device__ int   g_cnt [N_NODES];                // histogram, then cursor
__device__ int   g_ptr [N_NODES + 1];            // row pointers
__device__ int   g_bsum[N_SCAN_BLOCKS];
__device__ int   g_flag[N_SCAN_BLOCKS];          // lookback ready flags
__device__ int2  g_edge[N_EDGES];                // {col, __float_as_int(w)}

// ---------------------------------------------------------------------------
// f32x2 packed math (sm_103a; PTX-only — ptxas never auto-fuses)
// ---------------------------------------------------------------------------
__device__ __forceinline__ unsigned long long pack2(float x, float y) {
    unsigned long long r;
    asm("mov.b64 %0, {%1, %2};" : "=l"(r) : "f"(x), "f"(y));
    return r;
}
__device__ __forceinline__ void unpack2(unsigned long long v, float& x, float& y) {
    asm("mov.b64 {%0, %1}, %2;" : "=f"(x), "=f"(y) : "l"(v));
}
__device__ __forceinline__ void fma2(unsigned long long& d,
                                     unsigned long long a,
                                     unsigned long long b) {
    asm("fma.rn.f32x2 %0, %1, %2, %0;" : "+l"(d) : "l"(a), "l"(b));
}

// ---------------------------------------------------------------------------
// dtype probe (thread 0) + zero histogram + zero scan flags
// ---------------------------------------------------------------------------
__global__ void detect_zero_kernel(const void* __restrict__ src) {
    int i = blockIdx.x * blockDim.x + threadIdx.x;
    if (i < N_NODES) g_cnt[i] = 0;
    if (i < N_SCAN_BLOCKS) g_flag[i] = 0;
    if (i == 0) {
        const long long* p = (const long long*)src;
        int ok = 1;
        for (int k = 0; k < 64; k++) {
            long long v = p[k];
            if (v < 0 || v >= N_NODES) { ok = 0; break; }
        }
        g_is64 = ok;
    }
}

__device__ __forceinline__ int load_idx(const void* p, int e, int is64) {
    return is64 ? (int)((const long long*)p)[e] : ((const int*)p)[e];
}

// ---------------------------------------------------------------------------
// CSR build: histogram -> single-pass scan (parallel lookback) -> scatter
// ---------------------------------------------------------------------------
__global__ void hist_kernel(const void* __restrict__ dst, int E) {
    int e = blockIdx.x * blockDim.x + threadIdx.x;
    if (e >= E) return;
    int d = load_idx(dst, e, g_is64);
    if ((unsigned)d < N_NODES) atomicAdd(&g_cnt[d], 1);
}

// One kernel: per-block inclusive scan + publish + parallel lookback.
// 98 blocks of 1024 threads — all resident in wave 1, no deadlock.
__global__ void scan_fused_kernel(int E) {
    __shared__ int s[SCAN_BLK];
    __shared__ int pre[128];
    const int b   = blockIdx.x;
    const int tid = threadIdx.x;
    const int i   = b * SCAN_BLK + tid;

    int v = (i < N_NODES) ? g_cnt[i] : 0;
    s[tid] = v;
    __syncthreads();
#pragma unroll
    for (int o = 1; o < SCAN_BLK; o <<= 1) {
        int t = (tid >= o) ? s[tid - o] : 0;
        __syncthreads();
        s[tid] += t;
        __syncthreads();
    }
    int inc = s[tid];

    if (tid == SCAN_BLK - 1) {
        g_bsum[b] = inc;
        __threadfence();
        atomicExch(&g_flag[b], 1);
    }

    if (tid < 128) {
        int sum = 0;
        if (tid < b) {
            while (atomicAdd(&g_flag[tid], 0) == 0) {}
            sum = g_bsum[tid];
        }
        pre[tid] = sum;
    }
    __syncthreads();
#pragma unroll
    for (int o = 64; o >= 1; o >>= 1) {
        if (tid < o) pre[tid] += pre[tid + o];
        __syncthreads();
    }
    int prefix = pre[0];

    if (i < N_NODES) {
        int p = prefix + inc - v;
        g_ptr[i] = p;
        g_cnt[i] = p;
    }
    if (i == 0) g_ptr[N_NODES] = E;
}

__global__ void scatter_kernel(const void* __restrict__ src,
                               const void* __restrict__ dst,
                               const float* __restrict__ w, int E) {
    int e = blockIdx.x * blockDim.x + threadIdx.x;
    if (e >= E) return;
    int is64 = g_is64;
    int s = load_idx(src, e, is64);
    int d = load_idx(dst, e, is64);
    if ((unsigned)s >= N_NODES || (unsigned)d >= N_NODES) return;
    float wt = __ldcs(w + e);                    // read-once stream
    int pos = atomicAdd(&g_cnt[d], 1);
    g_edge[pos] = make_int2(s, __float_as_int(wt));
}

// ---------------------------------------------------------------------------
// GEMM1: tensor-core (wmma fp16 in / fp32 accum), output fp16.
// xw0h[M,128] = fp16( X[M,256] @ W0[256,128] )
// ---------------------------------------------------------------------------
#define G1_LDA 40    // 32 + 8 halves
#define G1_LDB 136   // 128 + 8 halves
#define G1_LDC 72    // 64 + 8 floats (epilogue staging, per column-half)
#define G1_C_BYTES  (128 * G1_LDC * 4)                     // 36864

__global__ void gemm1_wmma_kernel(const float* __restrict__ X,
                                  const float* __restrict__ W0) {
    __shared__ __align__(16) char smem[G1_C_BYTES];        // 36 KB (union)
    half*  As = (half*)smem;                               // [128][40]
    half*  Bs = (half*)(smem + 128 * G1_LDA * 2);          // [32][136]
    float* Cs = (float*)smem;                              // [128][72]

    const int tid   = threadIdx.x;
    const int warp  = tid >> 5;
    const int warpM = warp >> 1;        // 0..3
    const int warpN = warp & 1;         // 0..1
    const int bm    = blockIdx.x * 128;

    wmma::fragment<wmma::accumulator, 16, 16, 16, float> c[2][4];
#pragma unroll
    for (int i = 0; i < 2; i++)
#pragma unroll
        for (int j = 0; j < 4; j++) wmma::fill_fragment(c[i][j], 0.f);

    for (int k0 = 0; k0 < D_FEAT; k0 += 32) {
        // As: 128x32 fp32 -> fp16 (X read once -> streaming)
#pragma unroll
        for (int t = 0; t < 4; t++) {
            int chunk = tid + t * 256;
            int row = chunk >> 3;
            int c4  = chunk & 7;
            int grow = bm + row;
            float4 v = make_float4(0.f, 0.f, 0.f, 0.f);
            if (grow < N_NODES)
                v = __ldcs((const float4*)(X + (size_t)grow * D_FEAT + k0 + c4 * 4));
            __half2 h0 = __floats2half2_rn(v.x, v.y);
            __half2 h1 = __floats2half2_rn(v.z, v.w);
            uint2 pk;
            pk.x = *(unsigned*)&h0;
            pk.y = *(unsigned*)&h1;
            *(uint2*)(As + (size_t)row * G1_LDA + c4 * 4) = pk;
        }
        // Bs: 32x128 fp32 -> fp16
#pragma unroll
        for (int t = 0; t < 4; t++) {
            int chunk = tid + t * 256;
            int row = chunk >> 5;
            int c4  = chunk & 31;
            float4 v = *(const float4*)(W0 + (size_t)(k0 + row) * H1 + c4 * 4);
            __half2 h0 = __floats2half2_rn(v.x, v.y);
            __half2 h1 = __floats2half2_rn(v.z, v.w);
            uint2 pk;
            pk.x = *(unsigned*)&h0;
            pk.y = *(unsigned*)&h1;
            *(uint2*)(Bs + (size_t)row * G1_LDB + c4 * 4) = pk;
        }
        __syncthreads();

#pragma unroll
        for (int kk = 0; kk < 32; kk += 16) {
            wmma::fragment<wmma::matrix_a, 16, 16, 16, half, wmma::row_major> a[2];
            wmma::fragment<wmma::matrix_b, 16, 16, 16, half, wmma::row_major> b[4];
#pragma unroll
            for (int i = 0; i < 2; i++)
                wmma::load_matrix_sync(a[i],
                    As + (size_t)(warpM * 32 + i * 16) * G1_LDA + kk, G1_LDA);
#pragma unroll
            for (int j = 0; j < 4; j++)
                wmma::load_matrix_sync(b[j],
                    Bs + (size_t)kk * G1_LDB + warpN * 64 + j * 16, G1_LDB);
#pragma unroll
            for (int i = 0; i < 2; i++)
#pragma unroll
                for (int j = 0; j < 4; j++)
                    wmma::mma_sync(c[i][j], a[i], b[j], c[i][j]);
        }
        __syncthreads();
    }

    // Epilogue in two column-halves through smem staging
#pragma unroll
    for (int p = 0; p < 2; p++) {
        if (warpN == p) {
#pragma unroll
            for (int i = 0; i < 2; i++)
#pragma unroll
                for (int j = 0; j < 4; j++)
                    wmma::store_matrix_sync(
                        Cs + (size_t)(warpM * 32 + i * 16) * G1_LDC + j * 16,
                        c[i][j], G1_LDC, wmma::mem_row_major);
        }
        __syncthreads();
#pragma unroll
        for (int t = 0; t < 8; t++) {
            int chunk = tid + t * 256;
            int row = chunk >> 4;
            int c4  = chunk & 15;
            int grow = bm + row;
            if (grow < N_NODES) {
                const float* s = Cs + (size_t)row * G1_LDC + c4 * 4;
                __half2 h0 = __floats2half2_rn(s[0], s[1]);
                __half2 h1 = __floats2half2_rn(s[2], s[3]);
                uint2 pk;
                pk.x = *(unsigned*)&h0;
                pk.y = *(unsigned*)&h1;
                *(uint2*)(g_xw0h + (size_t)grow * H1 + p * 64 + c4 * 4) = pk;
            }
        }
        __syncthreads();
    }
}

// ---------------------------------------------------------------------------
// GEMM2 (f32x2, register-blocked, fp32 A-path — precision-critical):
// hw1h[M,64] = fp16( relu(h1) @ W1 );  A read once -> streaming loads
// ---------------------------------------------------------------------------
template<int BM, int BN, int BK, int TM, int TN, bool RELU_A>
__device__ __forceinline__ void gemm_body_h(const float* __restrict__ A,
                                            const float* __restrict__ B,
                                            __half* __restrict__ C,
                                            int M, int K, int N)
{
    __shared__ float As[BK][BM];   // transposed A tile
    __shared__ float Bs[BK][BN];

    constexpr int THREADS = (BM / TM) * (BN / TN);   // 256
    const int tid = threadIdx.x;
    const int bm  = blockIdx.x * BM;
    const int tx  = tid % (BN / TN);
    const int ty  = tid / (BN / TN);

    unsigned long long acc2[TM][TN / 2];
#pragma unroll
    for (int i = 0; i < TM; i++)
#pragma unroll
        for (int j = 0; j < TN / 2; j++) acc2[i][j] = 0ull;

    for (int k0 = 0; k0 < K; k0 += BK) {
        constexpr int A_ELEMS = BM * BK;
#pragma unroll
        for (int off = 0; off < A_ELEMS; off += THREADS * 4) {
            int idx = off + tid * 4;
            if (idx < A_ELEMS) {
                int ar  = idx / BK;
                int ac  = idx % BK;
                int grow = bm + ar;
                float4 v = make_float4(0.f, 0.f, 0.f, 0.f);
                if (grow < M)
                    v = __ldcs((const float4*)(A + (size_t)grow * K + k0 + ac));
                if (RELU_A) {
                    v.x = fmaxf(v.x, 0.f); v.y = fmaxf(v.y, 0.f);
                    v.z = fmaxf(v.z, 0.f); v.w = fmaxf(v.w, 0.f);
                }
                As[ac + 0][ar] = v.x;
                As[ac + 1][ar] = v.y;
                As[ac + 2][ar] = v.z;
                As[ac + 3][ar] = v.w;
            }
        }
        constexpr int B_ELEMS = BK * BN;
#pragma unroll
        for (int off = 0; off < B_ELEMS; off += THREADS * 4) {
            int idx = off + tid * 4;
            if (idx < B_ELEMS) {
                int br = idx / BN;
                int bc = idx % BN;
                *(float4*)&Bs[br][bc] =
                    *(const float4*)(B + (size_t)(k0 + br) * N + bc);
            }
        }
        __syncthreads();

#pragma unroll
        for (int kk = 0; kk < BK; kk++) {
            unsigned long long b2[TN / 2];
#pragma unroll
            for (int j = 0; j < TN / 2; j++)
                b2[j] = *(const unsigned long long*)&Bs[kk][tx * TN + 2 * j];
#pragma unroll
            for (int i = 0; i < TM; i++) {
                float a = As[kk][ty * TM + i];
                unsigned long long a2 = pack2(a, a);
#pragma unroll
                for (int j = 0; j < TN / 2; j++)
                    fma2(acc2[i][j], a2, b2[j]);
            }
        }
        __syncthreads();
    }

#pragma unroll
    for (int i = 0; i < TM; i++) {
        int row = bm + ty * TM + i;
        if (row < M) {
            __half2 h[TN / 2];
#pragma unroll
            for (int j = 0; j < TN / 2; j++) {
                float lo, hi;
                unpack2(acc2[i][j], lo, hi);
                h[j] = __floats2half2_rn(lo, hi);
            }
#pragma unroll
            for (int j = 0; j < TN / 2; j += 2)
                *(uint2*)(C + (size_t)row * N + tx * TN + 2 * j) =
                    *(uint2*)&h[j];
        }
    }
}

__global__ void gemm2_kernel(const float* __restrict__ W1) {
    gemm_body_h<128, 64, 32, 8, 4, true>(g_h1, W1, g_hw1h, N_NODES, H1, H2);
}

// ---------------------------------------------------------------------------
// CSR SPMM layer 1: h1[r] = sum_e w_e * xw0[col_e], F=128 halves.
// One warp per row; 16-edge batches for deep MLP; streaming h1 stores
// (keeps g_xw0h resident in L2 while the 51 MB h1 stream passes through).
// ---------------------------------------------------------------------------
__global__ void spmm1_csr_kernel()
{
    int warp = (int)(((long long)blockIdx.x * blockDim.x + threadIdx.x) >> 5);
    int lane = threadIdx.x & 31;
    if (warp >= N_NODES) return;
    int p  = g_ptr[warp];
    int pe = g_ptr[warp + 1];
    const uint2* __restrict__ h4 = (const uint2*)g_xw0h;   // 4 halves / elem
    float4 acc = make_float4(0.f, 0.f, 0.f, 0.f);

    for (; p + 16 <= pe; p += 16) {
        int2  e[16];
        uint2 r[16];
#pragma unroll
        for (int j = 0; j < 16; j++) e[j] = g_edge[p + j];
#pragma unroll
        for (int j = 0; j < 16; j++) r[j] = h4[(size_t)e[j].x * 32 + lane];
#pragma unroll
        for (int j = 0; j < 16; j++) {
            float w = __int_as_float(e[j].y);
            float2 a = __half22float2(*(__half2*)&r[j].x);
            float2 b = __half22float2(*(__half2*)&r[j].y);
            acc.x += w * a.x; acc.y += w * a.y;
            acc.z += w * b.x; acc.w += w * b.y;
        }
    }
    if (p + 8 <= pe) {
        int2  e[8];
        uint2 r[8];
#pragma unroll
        for (int j = 0; j < 8; j++) e[j] = g_edge[p + j];
#pragma unroll
        for (int j = 0; j < 8; j++) r[j] = h4[(size_t)e[j].x * 32 + lane];
#pragma unroll
        for (int j = 0; j < 8; j++) {
            float w = __int_as_float(e[j].y);
            float2 a = __half22float2(*(__half2*)&r[j].x);
            float2 b = __half22float2(*(__half2*)&r[j].y);
            acc.x += w * a.x; acc.y += w * a.y;
            acc.z += w * b.x; acc.w += w * b.y;
        }
        p += 8;
    }
    if (p + 4 <= pe) {
        int2  e[4];
        uint2 r[4];
#pragma unroll
        for (int j = 0; j < 4; j++) e[j] = g_edge[p + j];
#pragma unroll
        for (int j = 0; j < 4; j++) r[j] = h4[(size_t)e[j].x * 32 + lane];
#pragma unroll
        for (int j = 0; j < 4; j++) {
            float w = __int_as_float(e[j].y);
            float2 a = __half22float2(*(__half2*)&r[j].x);
            float2 b = __half22float2(*(__half2*)&r[j].y);
            acc.x += w * a.x; acc.y += w * a.y;
            acc.z += w * b.x; acc.w += w * b.y;
        }
        p += 4;
    }
    for (; p < pe; p++) {
        int2 e = g_edge[p];
        float w = __int_as_float(e.y);
        uint2 r = h4[(size_t)e.x * 32 + lane];
        float2 a = __half22float2(*(__half2*)&r.x);
        float2 b = __half22float2(*(__half2*)&r.y);
        acc.x += w * a.x; acc.y += w * a.y;
        acc.z += w * b.x; acc.w += w * b.y;
    }
    __stcs((float4*)g_h1 + (size_t)warp * 32 + lane, acc);   // evict-first
}

// ---------------------------------------------------------------------------
// CSR SPMM layer 2 fused with relu + softmax, F=64 halves; 8-edge batches.
// Edge list: last reader -> streaming loads. Output: write-once -> streaming.
// ---------------------------------------------------------------------------
__global__ void spmm2_softmax_kernel(float* __restrict__ out)
{
    int warp = (int)(((long long)blockIdx.x * blockDim.x + threadIdx.x) >> 5);
    int lane = threadIdx.x & 31;
    if (warp >= N_NODES) return;
    int p  = g_ptr[warp];
    int pe = g_ptr[warp + 1];
    const unsigned* __restrict__ h2p = (const unsigned*)g_hw1h;  // 2 halves
    float2 acc = make_float2(0.f, 0.f);

    for (; p + 8 <= pe; p += 8) {
        int2     e[8];
        unsigned r[8];
#pragma unroll
        for (int j = 0; j < 8; j++) e[j] = __ldcs(&g_edge[p + j]);
#pragma unroll
        for (int j = 0; j < 8; j++) r[j] = h2p[(size_t)e[j].x * 32 + lane];
#pragma unroll
        for (int j = 0; j < 8; j++) {
            float w = __int_as_float(e[j].y);
            float2 v = __half22float2(*(__half2*)&r[j]);
            acc.x += w * v.x; acc.y += w * v.y;
        }
    }
    if (p + 4 <= pe) {
        int2     e[4];
        unsigned r[4];
#pragma unroll
        for (int j = 0; j < 4; j++) e[j] = __ldcs(&g_edge[p + j]);
#pragma unroll
        for (int j = 0; j < 4; j++) r[j] = h2p[(size_t)e[j].x * 32 + lane];
#pragma unroll
        for (int j = 0; j < 4; j++) {
            float w = __int_as_float(e[j].y);
            float2 v = __half22float2(*(__half2*)&r[j]);
            acc.x += w * v.x; acc.y += w * v.y;
        }
        p += 4;
    }
    for (; p < pe; p++) {
        int2 e = __ldcs(&g_edge[p]);
        float w = __int_as_float(e.y);
        unsigned r = h2p[(size_t)e.x * 32 + lane];
        float2 v = __half22float2(*(__half2*)&r);
        acc.x += w * v.x; acc.y += w * v.y;
    }

    // relu + softmax over the 64 values held by the warp
    float v0 = fmaxf(acc.x, 0.f);
    float v1 = fmaxf(acc.y, 0.f);
    float m = fmaxf(v0, v1);
#pragma unroll
    for (int o = 16; o; o >>= 1) m = fmaxf(m, __shfl_xor_sync(~0u, m, o));
    float e0 = __expf(v0 - m);
    float e1 = __expf(v1 - m);
    float s = e0 + e1;
#pragma unroll
    for (int o = 16; o; o >>= 1) s += __shfl_xor_sync(~0u, s, o);
    float inv = 1.f / s;
    __stcs((float2*)out + (size_t)warp * 32 + lane,
           make_float2(e0 * inv, e1 * inv));
}

// ---------------------------------------------------------------------------
// Launch: fork-join streams — gemm1 (tensor) overlaps CSR build (memory)
// ---------------------------------------------------------------------------
extern "C" void kernel_launch(void* const* d_in, const int* in_sizes, int n_in,
                              void* d_out, int out_size)
{
    // Identify inputs by element count (same logic that passed R3-R12).
    const float* x  = nullptr;
    const float* W0 = nullptr;
    const float* W1 = nullptr;
    const void*  edge_buf[3] = {nullptr, nullptr, nullptr};
    int          edge_sz [3] = {0, 0, 0};
    int n_edge_bufs = 0;

    for (int i = 0; i < n_in; i++) {
        int sz = in_sizes[i];
        if (sz == N_NODES * D_FEAT)       x  = (const float*)d_in[i];
        else if (sz == D_FEAT * H1)       W0 = (const float*)d_in[i];
        else if (sz == H1 * H2)           W1 = (const float*)d_in[i];
        else if (n_edge_bufs < 3) {
            edge_buf[n_edge_bufs] = d_in[i];
            edge_sz [n_edge_bufs] = sz;
            n_edge_bufs++;
        }
    }
    const void*  esrc = edge_buf[0];
    const void*  edst = edge_buf[1];
    const float* ew   = (const float*)edge_buf[2];
    if (edge_sz[0] != edge_sz[1] || edge_sz[1] != edge_sz[2]) {
        int wi = 0;
        if (edge_sz[1] < edge_sz[wi]) wi = 1;
        if (edge_sz[2] < edge_sz[wi]) wi = 2;
        const void* rest[2]; int r = 0;
        for (int i = 0; i < 3; i++) if (i != wi) rest[r++] = edge_buf[i];
        esrc = rest[0]; edst = rest[1];
        ew   = (const float*)edge_buf[wi];
    }
    float* out = (float*)d_out;
    const int E = N_EDGES;

    const int EBLK = (E + 255) / 256;
    const int NBLK = (N_NODES + 255) / 256;
    const int WBLK = (int)(((long long)N_NODES * 32 + 255) / 256);

    // Fork-join side stream for gemm1 (created/destroyed per call; no caching)
    cudaStream_t s2 = nullptr;
    cudaEvent_t  evFork = nullptr, evJoin = nullptr;
    bool overlap = (cudaStreamCreateWithFlags(&s2, cudaStreamNonBlocking)
                        == cudaSuccess);
    if (overlap) {
        overlap = (cudaEventCreateWithFlags(&evFork, cudaEventDisableTiming)
                       == cudaSuccess) &&
                  (cudaEventCreateWithFlags(&evJoin, cudaEventDisableTiming)
                       == cudaSuccess);
    }

    if (overlap) {
        cudaEventRecord(evFork, 0);            // fork from capture stream
        cudaStreamWaitEvent(s2, evFork, 0);
        gemm1_wmma_kernel<<<(N_NODES + 127) / 128, 256, 0, s2>>>(x, W0);
        cudaEventRecord(evJoin, s2);
    } else {
        gemm1_wmma_kernel<<<(N_NODES + 127) / 128, 256>>>(x, W0);
    }

    // CSR build on the main (capture) stream
    detect_zero_kernel<<<NBLK, 256>>>(esrc);
    hist_kernel<<<EBLK, 256>>>(edst, E);
    scan_fused_kernel<<<N_SCAN_BLOCKS, SCAN_BLK>>>(E);
    scatter_kernel<<<EBLK, 256>>>(esrc, edst, ew, E);

    if (overlap)
        cudaStreamWaitEvent(0, evJoin, 0);     // join before spmm1

    // layer 1 aggregate: h1 = A @ xw0 (CSR gather, fp32 acc)
    spmm1_csr_kernel<<<WBLK, 256>>>();

    // layer 2: hw1h = fp16(relu(h1) @ W1), f32x2 path (precision-critical)
    gemm2_kernel<<<(N_NODES + 127) / 128, 256>>>(W1);

    // layer 2 aggregate + softmax: out = softmax(relu(A @ hw1))
    spmm2_softmax_kernel<<<WBLK, 256>>>(out);

    if (evFork) cudaEventDestroy(evFork);
    if (evJoin) cudaEventDestroy(evJoin);
    if (s2)     cudaStreamDestroy(s2);
}